// round 4
// baseline (speedup 1.0000x reference)
#include <cuda_runtime.h>
#include <math.h>

#define TT 256
#define BB 256
#define DIN 129        // D+1
#define HH 512
#define GG 1536        // 3*H
#define N1 1280        // 10*D
#define K1 513         // H+1
#define DOUT 128
#define TM1 255        // T-1
#define M_PRE (BB*TM1) // 65280
#define OFF_DIST ((size_t)M_PRE*DOUT)            // 8,355,840
#define OFF_LEN  (OFF_DIST + (size_t)BB*3)       // 8,356,608

// ---------------- scratch (static device globals; no runtime allocation) ----
__device__ float g_xw[(size_t)TT*BB*GG];     // (t,b,g)  402 MB
__device__ float g_hidden[(size_t)BB*TT*HH]; // (b,t,h)  134 MB
__device__ float g_hA[BB*HH];
__device__ float g_hB[BB*HH];
__device__ float g_pre[(size_t)M_PRE*N1];    // (row,n)  334 MB

__device__ __forceinline__ float sigmoidf_(float x){ return 1.0f/(1.0f+expf(-x)); }

// ---------------------------------------------------------------------------
// Kernel 1: xw[t,b,g] = sum_d x[t,b,d]*w_ih[g,d] + b_ih[g]
// M=65536, N=1536, K=129.  64x64 tile, 256 thr, 4x4 micro.
// ---------------------------------------------------------------------------
__global__ __launch_bounds__(256) void gemm_xw(
    const float* __restrict__ X, const float* __restrict__ W,
    const float* __restrict__ bias, float* __restrict__ out)
{
    __shared__ float As[32][68];
    __shared__ float Bs[32][68];
    const int bm = blockIdx.y*64;
    const int bn = blockIdx.x*64;
    const int tid = threadIdx.x;
    const int tx = tid & 15, ty = tid >> 4;
    float acc[4][4] = {};
    for (int k0 = 0; k0 < DIN; k0 += 32){
        #pragma unroll
        for (int i=0;i<8;i++){
            int idx = tid + i*256;
            int kk = idx & 31, mm = idx >> 5;
            As[kk][mm] = (k0+kk < DIN) ? X[(size_t)(bm+mm)*DIN + k0+kk] : 0.f;
        }
        #pragma unroll
        for (int i=0;i<8;i++){
            int idx = tid + i*256;
            int kk = idx & 31, nn = idx >> 5;
            Bs[kk][nn] = (k0+kk < DIN) ? W[(size_t)(bn+nn)*DIN + k0+kk] : 0.f;
        }
        __syncthreads();
        #pragma unroll
        for (int kk=0;kk<32;kk++){
            float4 a = *(const float4*)&As[kk][ty*4];
            float4 b = *(const float4*)&Bs[kk][tx*4];
            float av[4] = {a.x,a.y,a.z,a.w};
            float bv[4] = {b.x,b.y,b.z,b.w};
            #pragma unroll
            for (int i=0;i<4;i++)
                #pragma unroll
                for (int j=0;j<4;j++)
                    acc[i][j] += av[i]*bv[j];
        }
        __syncthreads();
    }
    #pragma unroll
    for (int i=0;i<4;i++){
        int m = bm + ty*4 + i;
        #pragma unroll
        for (int j=0;j<4;j++){
            int n = bn + tx*4 + j;
            out[(size_t)m*GG + n] = acc[i][j] + bias[n];
        }
    }
}

// ---------------------------------------------------------------------------
// Kernel 2: one GRU time step, fused hw-GEMM (3 gates) + gate math.
// grid (H/32, B/32) = (16,8) = 128 CTAs, 256 threads, each 2x2 x 3 gates.
// ---------------------------------------------------------------------------
__global__ __launch_bounds__(256) void gru_step(
    const float* __restrict__ xw_t, const float* __restrict__ h_prev,
    float* __restrict__ h_next, float* __restrict__ hidden,
    const float* __restrict__ w_hh, const float* __restrict__ b_hh,
    const int* __restrict__ lengths, int t)
{
    __shared__ float hs[32][33];
    __shared__ float ws[3][32][33];
    const int bj = blockIdx.x*32;   // output h tile
    const int bb = blockIdx.y*32;   // batch tile
    const int tid = threadIdx.x;
    const int tx = tid & 15, ty = tid >> 4;
    float accr[2][2]={}, accz[2][2]={}, accn[2][2]={};

    for (int k0=0;k0<HH;k0+=32){
        #pragma unroll
        for (int i=0;i<4;i++){
            int idx = tid + i*256;
            int kk = idx & 31, r = idx >> 5;
            hs[kk][r] = h_prev[(bb+r)*HH + k0+kk];
        }
        #pragma unroll
        for (int i=0;i<12;i++){
            int idx = tid + i*256;
            int kk = idx & 31, r = idx >> 5;   // 0..95
            int gg = r >> 5, nn = r & 31;
            ws[gg][kk][nn] = w_hh[(size_t)(gg*HH + bj + nn)*HH + k0+kk];
        }
        __syncthreads();
        #pragma unroll
        for (int kk=0;kk<32;kk++){
            float h0 = hs[kk][2*ty], h1 = hs[kk][2*ty+1];
            float wr0 = ws[0][kk][2*tx], wr1 = ws[0][kk][2*tx+1];
            float wz0 = ws[1][kk][2*tx], wz1 = ws[1][kk][2*tx+1];
            float wn0 = ws[2][kk][2*tx], wn1 = ws[2][kk][2*tx+1];
            accr[0][0]+=h0*wr0; accr[0][1]+=h0*wr1; accr[1][0]+=h1*wr0; accr[1][1]+=h1*wr1;
            accz[0][0]+=h0*wz0; accz[0][1]+=h0*wz1; accz[1][0]+=h1*wz0; accz[1][1]+=h1*wz1;
            accn[0][0]+=h0*wn0; accn[0][1]+=h0*wn1; accn[1][0]+=h1*wn0; accn[1][1]+=h1*wn1;
        }
        __syncthreads();
    }

    #pragma unroll
    for (int i=0;i<2;i++){
        int b = bb + 2*ty + i;
        bool valid = t < lengths[b];
        #pragma unroll
        for (int j=0;j<2;j++){
            int jj = bj + 2*tx + j;
            float xr = xw_t[(size_t)b*GG + jj];
            float xz = xw_t[(size_t)b*GG + HH + jj];
            float xn = xw_t[(size_t)b*GG + 2*HH + jj];
            float r = sigmoidf_(xr + accr[i][j] + b_hh[jj]);
            float z = sigmoidf_(xz + accz[i][j] + b_hh[HH+jj]);
            float n = tanhf(xn + r*(accn[i][j] + b_hh[2*HH+jj]));
            float hp = h_prev[b*HH + jj];
            float hv = (1.f - z)*n + z*hp;
            h_next[b*HH + jj] = valid ? hv : hp;
            hidden[(size_t)b*(TT*HH) + (size_t)t*HH + jj] = valid ? hv : 0.f;
        }
    }
}

// ---------------------------------------------------------------------------
// Kernel 3: pre[row,n] = sigmoid( hwt[row,:] . w1[n,:] + b1[n] )
// hwt[row,k] = hidden[b,t,k] for k<512, td(b,t) for k==512.
// M=65280, N=1280, K=513.
// ---------------------------------------------------------------------------
__global__ __launch_bounds__(256) void gemm_pre(
    const float* __restrict__ hidden, const float* __restrict__ X,
    const float* __restrict__ W1, const float* __restrict__ b1,
    float* __restrict__ pre)
{
    __shared__ float As[32][68];
    __shared__ float Bs[32][68];
    const int bm = blockIdx.y*64;
    const int bn = blockIdx.x*64;
    const int tid = threadIdx.x;
    const int tx = tid & 15, ty = tid >> 4;
    float acc[4][4] = {};
    for (int k0 = 0; k0 < K1; k0 += 32){
        #pragma unroll
        for (int i=0;i<8;i++){
            int idx = tid + i*256;
            int kk = idx & 31, mm = idx >> 5;
            int k = k0 + kk;
            int row = bm + mm;
            int b = row / TM1;
            int tt = row - b*TM1;
            float v = 0.f;
            if (k < HH){
                v = hidden[(size_t)b*(TT*HH) + (size_t)tt*HH + k];
            } else if (k == HH){
                v = X[(size_t)(tt+1)*BB*DIN + (size_t)b*DIN]
                  - X[(size_t)tt*BB*DIN + (size_t)b*DIN];
            }
            As[kk][mm] = v;
        }
        #pragma unroll
        for (int i=0;i<8;i++){
            int idx = tid + i*256;
            int kk = idx & 31, nn = idx >> 5;
            Bs[kk][nn] = (k0+kk < K1) ? W1[(size_t)(bn+nn)*K1 + k0+kk] : 0.f;
        }
        __syncthreads();
        #pragma unroll
        for (int kk=0;kk<32;kk++){
            float4 a = *(const float4*)&As[kk][ty*4];
            float4 b = *(const float4*)&Bs[kk][tx*4];
            float av[4] = {a.x,a.y,a.z,a.w};
            float bv[4] = {b.x,b.y,b.z,b.w};
            #pragma unroll
            for (int i=0;i<4;i++)
                #pragma unroll
                for (int j=0;j<4;j++)
                    acc[i][j] += av[i]*bv[j];
        }
        __syncthreads();
    }
    #pragma unroll
    for (int i=0;i<4;i++){
        int row = bm + ty*4 + i;
        #pragma unroll
        for (int j=0;j<4;j++){
            int n = bn + tx*4 + j;
            pre[(size_t)row*N1 + n] = sigmoidf_(acc[i][j] + b1[n]);
        }
    }
}

// ---------------------------------------------------------------------------
// Kernel 4: preds[row,d] = mask ? pre[row,:] . w2[d,:] + b2[d] : 0
// M=65280, N=128, K=1280.  Writes directly into d_out.
// ---------------------------------------------------------------------------
__global__ __launch_bounds__(256) void gemm_preds(
    const float* __restrict__ pre, const float* __restrict__ W2,
    const float* __restrict__ b2, const int* __restrict__ lengths,
    float* __restrict__ out)
{
    __shared__ float As[32][68];
    __shared__ float Bs[32][68];
    const int bm = blockIdx.y*64;
    const int bn = blockIdx.x*64;
    const int tid = threadIdx.x;
    const int tx = tid & 15, ty = tid >> 4;
    float acc[4][4] = {};
    for (int k0 = 0; k0 < N1; k0 += 32){
        #pragma unroll
        for (int i=0;i<8;i++){
            int idx = tid + i*256;
            int kk = idx & 31, mm = idx >> 5;
            As[kk][mm] = pre[(size_t)(bm+mm)*N1 + k0+kk];
        }
        #pragma unroll
        for (int i=0;i<8;i++){
            int idx = tid + i*256;
            int kk = idx & 31, nn = idx >> 5;
            Bs[kk][nn] = W2[(size_t)(bn+nn)*N1 + k0+kk];
        }
        __syncthreads();
        #pragma unroll
        for (int kk=0;kk<32;kk++){
            float4 a = *(const float4*)&As[kk][ty*4];
            float4 b = *(const float4*)&Bs[kk][tx*4];
            float av[4] = {a.x,a.y,a.z,a.w};
            float bv[4] = {b.x,b.y,b.z,b.w};
            #pragma unroll
            for (int i=0;i<4;i++)
                #pragma unroll
                for (int j=0;j<4;j++)
                    acc[i][j] += av[i]*bv[j];
        }
        __syncthreads();
    }
    #pragma unroll
    for (int i=0;i<4;i++){
        int row = bm + ty*4 + i;
        int b = row / TM1;
        int tt = row - b*TM1;
        bool m = tt < (lengths[b] - 1);
        #pragma unroll
        for (int j=0;j<4;j++){
            int n = bn + tx*4 + j;
            out[(size_t)row*DOUT + n] = m ? (acc[i][j] + b2[n]) : 0.f;
        }
    }
}

// ---------------------------------------------------------------------------
// Kernel 5: dist_params[b,p] = exp(-(h_last[b,:].wp[p,:] + bp[p]));
//           out lengths as float.
// ---------------------------------------------------------------------------
__global__ __launch_bounds__(256) void finalize_k(
    const float* __restrict__ h_last, const float* __restrict__ wp,
    const float* __restrict__ bp, const int* __restrict__ lengths,
    float* __restrict__ out)
{
    int b = threadIdx.x;
    if (b < BB){
        #pragma unroll
        for (int p=0;p<3;p++){
            float dot = 0.f;
            for (int h=0;h<HH;h++) dot += h_last[b*HH + h]*wp[p*HH + h];
            out[OFF_DIST + (size_t)b*3 + p] = expf(-(dot + bp[p]));
        }
        out[OFF_LEN + b] = (float)lengths[b];
    }
}

// ---------------------------------------------------------------------------
extern "C" void kernel_launch(void* const* d_in, const int* in_sizes, int n_in,
                              void* d_out, int out_size)
{
    const float* x    = (const float*)d_in[0];
    const float* h0   = (const float*)d_in[1];
    const int*   len  = (const int*)d_in[2];
    const float* w_ih = (const float*)d_in[3];
    const float* w_hh = (const float*)d_in[4];
    const float* b_ih = (const float*)d_in[5];
    const float* b_hh = (const float*)d_in[6];
    const float* w1   = (const float*)d_in[7];
    const float* b1   = (const float*)d_in[8];
    const float* w2   = (const float*)d_in[9];
    const float* b2   = (const float*)d_in[10];
    const float* wp   = (const float*)d_in[11];
    const float* bp   = (const float*)d_in[12];
    float* out = (float*)d_out;

    float *xw, *hidden, *hA, *hB, *pre;
    cudaGetSymbolAddress((void**)&xw,     g_xw);
    cudaGetSymbolAddress((void**)&hidden, g_hidden);
    cudaGetSymbolAddress((void**)&hA,     g_hA);
    cudaGetSymbolAddress((void**)&hB,     g_hB);
    cudaGetSymbolAddress((void**)&pre,    g_pre);

    // 1) input projection for all timesteps
    gemm_xw<<<dim3(GG/64, (TT*BB)/64), 256>>>(x, w_ih, b_ih, xw);

    // 2) sequential GRU with ping-pong h buffers
    const float* cur = h0;
    for (int t = 0; t < TT; t++){
        float* nxt = (t & 1) ? hB : hA;
        gru_step<<<dim3(HH/32, BB/32), 256>>>(
            xw + (size_t)t*BB*GG, cur, nxt, hidden, w_hh, b_hh, len, t);
        cur = nxt;
    }

    // 3) MLP head
    gemm_pre<<<dim3(N1/64, M_PRE/64), 256>>>(hidden, x, w1, b1, pre);
    gemm_preds<<<dim3(DOUT/64, M_PRE/64), 256>>>(pre, w2, b2, len, out);

    // 4) distribution head + lengths passthrough
    finalize_k<<<1, 256>>>(cur, wp, bp, len, out);
}

// round 6
// speedup vs baseline: 1.0143x; 1.0143x over previous
#include <cuda_runtime.h>
#include <math.h>

#define TT 256
#define BB 256
#define DIN 129        // D+1
#define HH 512
#define GG 1536        // 3*H
#define N1 1280        // 10*D
#define K1 513         // H+1
#define DOUT 128
#define TM1 255        // T-1
#define M_PRE (BB*TM1) // 65280
#define OFF_DIST ((size_t)M_PRE*DOUT)            // 8,355,840
#define OFF_LEN  (OFF_DIST + (size_t)BB*3)       // 8,356,608

typedef unsigned long long u64t;

// ---------------- packed f32x2 helpers (Blackwell dual-fp32 path) ----------
__device__ __forceinline__ void ffma2(u64t &d, u64t a, u64t b){
    asm("fma.rn.f32x2 %0, %1, %2, %0;" : "+l"(d) : "l"(a), "l"(b));
}
__device__ __forceinline__ u64t pk2(float x, float y){
    u64t r; asm("mov.b64 %0, {%1,%2};" : "=l"(r) : "f"(x), "f"(y)); return r;
}
__device__ __forceinline__ float2 upk2(u64t v){
    float lo, hi; asm("mov.b64 {%0,%1}, %2;" : "=f"(lo), "=f"(hi) : "l"(v));
    return make_float2(lo, hi);
}

// ---------------- scratch (static device globals; no runtime allocation) ----
__device__ float g_xw[(size_t)TT*BB*GG];     // (t,b,g)
__device__ float g_hidden[(size_t)BB*TT*HH]; // (b,t,h)
__device__ float g_hA[BB*HH];
__device__ float g_hB[BB*HH];
__device__ float g_pre[(size_t)M_PRE*N1];    // (row,n)

__device__ __forceinline__ float sigmoidf_(float x){ return 1.0f/(1.0f+expf(-x)); }

// ---------------------------------------------------------------------------
// Kernel 1: xw[t,b,g] = sum_d x[t,b,d]*w_ih[g,d] + b_ih[g]
// M=65536, N=1536, K=129.  64x64 tile, 256 thr, 4x4 micro, f32x2 FMA.
// ---------------------------------------------------------------------------
__global__ __launch_bounds__(256) void gemm_xw(
    const float* __restrict__ X, const float* __restrict__ W,
    const float* __restrict__ bias, float* __restrict__ out)
{
    __shared__ float As[32][68];
    __shared__ float Bs[32][68];
    const int bm = blockIdx.y*64;
    const int bn = blockIdx.x*64;
    const int tid = threadIdx.x;
    const int tx = tid & 15, ty = tid >> 4;
    u64t acc[4][2] = {};
    for (int k0 = 0; k0 < DIN; k0 += 32){
        #pragma unroll
        for (int i=0;i<8;i++){
            int idx = tid + i*256;
            int kk = idx & 31, mm = idx >> 5;
            As[kk][mm] = (k0+kk < DIN) ? X[(size_t)(bm+mm)*DIN + k0+kk] : 0.f;
        }
        #pragma unroll
        for (int i=0;i<8;i++){
            int idx = tid + i*256;
            int kk = idx & 31, nn = idx >> 5;
            Bs[kk][nn] = (k0+kk < DIN) ? W[(size_t)(bn+nn)*DIN + k0+kk] : 0.f;
        }
        __syncthreads();
        #pragma unroll
        for (int kk=0;kk<32;kk++){
            float4 a = *(const float4*)&As[kk][ty*4];
            ulonglong2 b = *(const ulonglong2*)&Bs[kk][tx*4];
            u64t pa0 = pk2(a.x,a.x), pa1 = pk2(a.y,a.y);
            u64t pa2 = pk2(a.z,a.z), pa3 = pk2(a.w,a.w);
            ffma2(acc[0][0], pa0, b.x); ffma2(acc[0][1], pa0, b.y);
            ffma2(acc[1][0], pa1, b.x); ffma2(acc[1][1], pa1, b.y);
            ffma2(acc[2][0], pa2, b.x); ffma2(acc[2][1], pa2, b.y);
            ffma2(acc[3][0], pa3, b.x); ffma2(acc[3][1], pa3, b.y);
        }
        __syncthreads();
    }
    #pragma unroll
    for (int i=0;i<4;i++){
        int m = bm + ty*4 + i;
        #pragma unroll
        for (int p=0;p<2;p++){
            float2 v = upk2(acc[i][p]);
            int n = bn + tx*4 + 2*p;
            out[(size_t)m*GG + n]     = v.x + bias[n];
            out[(size_t)m*GG + n + 1] = v.y + bias[n+1];
        }
    }
}

// ---------------------------------------------------------------------------
// Kernel 2: one GRU time step, fused hw-GEMM (3 gates) + gate math.
// grid (16 j-tiles, 8 b-tiles) = 128 CTAs, 256 thr.
// CTA tile: 32 batch x 96 gate-cols (32 cols per gate, all 3 gates).
// Micro: 2(m) x 6(n) via 6 f32x2 FMAs per k.
// ---------------------------------------------------------------------------
__global__ __launch_bounds__(256) void gru_step(
    const float* __restrict__ xw_t, const float* __restrict__ h_prev,
    float* __restrict__ h_next, float* __restrict__ hidden,
    const float* __restrict__ w_hh, const float* __restrict__ b_hh,
    const int* __restrict__ lengths, int t)
{
    __shared__ float hs[32][34];
    __shared__ float ws[32][98];   // reused as sacc[32 m][96 c] for epilogue
    const int bj = blockIdx.x*32;  // gate-local column tile base (0..480)
    const int bb = blockIdx.y*32;  // batch tile base
    const int tid = threadIdx.x;
    const int tx = tid & 15, ty = tid >> 4;
    u64t acc[2][3] = {};

    for (int k0=0;k0<HH;k0+=32){
        #pragma unroll
        for (int i=0;i<4;i++){
            int idx = tid + i*256;
            int kk = idx & 31, m = idx >> 5;
            hs[kk][m] = h_prev[(bb+m)*HH + k0+kk];
        }
        #pragma unroll
        for (int i=0;i<12;i++){
            int idx = tid + i*256;
            int kk = idx & 31, c = idx >> 5;   // c in [0,96)
            int g = c >> 5, jl = c & 31;
            ws[kk][c] = w_hh[(size_t)(g*HH + bj + jl)*HH + k0+kk];
        }
        __syncthreads();
        #pragma unroll
        for (int kk=0;kk<32;kk++){
            float2 a = *(const float2*)&hs[kk][2*ty];
            u64t pa0 = pk2(a.x,a.x), pa1 = pk2(a.y,a.y);
            const float* wr = &ws[kk][6*tx];
            u64t b0 = *(const u64t*)(wr);
            u64t b1 = *(const u64t*)(wr+2);
            u64t b2 = *(const u64t*)(wr+4);
            ffma2(acc[0][0], pa0, b0); ffma2(acc[0][1], pa0, b1); ffma2(acc[0][2], pa0, b2);
            ffma2(acc[1][0], pa1, b0); ffma2(acc[1][1], pa1, b1); ffma2(acc[1][2], pa1, b2);
        }
        __syncthreads();
    }

    // dump accumulators into smem (reuse ws) so each thread can gather r,z,n
    #pragma unroll
    for (int i=0;i<2;i++){
        int m = 2*ty + i;
        #pragma unroll
        for (int p=0;p<3;p++){
            float2 v = upk2(acc[i][p]);
            *(float2*)&ws[m][6*tx + 2*p] = v;
        }
    }
    __syncthreads();

    #pragma unroll
    for (int q=0;q<4;q++){
        int o  = tid + q*256;       // 1024 outputs
        int m  = o >> 5, jl = o & 31;
        int b  = bb + m, jj = bj + jl;
        float hr = ws[m][jl], hz = ws[m][32+jl], hn = ws[m][64+jl];
        float xr = xw_t[(size_t)b*GG + jj];
        float xz = xw_t[(size_t)b*GG + HH  + jj];
        float xn = xw_t[(size_t)b*GG + 2*HH + jj];
        float r = sigmoidf_(xr + hr + b_hh[jj]);
        float z = sigmoidf_(xz + hz + b_hh[HH+jj]);
        float n = tanhf(xn + r*(hn + b_hh[2*HH+jj]));
        float hp = h_prev[b*HH + jj];
        bool valid = t < lengths[b];
        float hv = (1.f - z)*n + z*hp;
        h_next[b*HH + jj] = valid ? hv : hp;
        hidden[(size_t)b*(TT*HH) + (size_t)t*HH + jj] = valid ? hv : 0.f;
    }
}

// ---------------------------------------------------------------------------
// Kernel 3: pre[row,n] = sigmoid( hwt[row,:] . w1[n,:] + b1[n] )
// M=65280, N=1280, K=513.  f32x2 micro.
// ---------------------------------------------------------------------------
__global__ __launch_bounds__(256) void gemm_pre(
    const float* __restrict__ hidden, const float* __restrict__ X,
    const float* __restrict__ W1, const float* __restrict__ b1,
    float* __restrict__ pre)
{
    __shared__ float As[32][68];
    __shared__ float Bs[32][68];
    const int bm = blockIdx.y*64;
    const int bn = blockIdx.x*64;
    const int tid = threadIdx.x;
    const int tx = tid & 15, ty = tid >> 4;
    u64t acc[4][2] = {};
    for (int k0 = 0; k0 < K1; k0 += 32){
        #pragma unroll
        for (int i=0;i<8;i++){
            int idx = tid + i*256;
            int kk = idx & 31, mm = idx >> 5;
            int k = k0 + kk;
            int row = bm + mm;
            int b = row / TM1;
            int tt = row - b*TM1;
            float v = 0.f;
            if (k < HH){
                v = hidden[(size_t)b*(TT*HH) + (size_t)tt*HH + k];
            } else if (k == HH){
                v = X[(size_t)(tt+1)*BB*DIN + (size_t)b*DIN]
                  - X[(size_t)tt*BB*DIN + (size_t)b*DIN];
            }
            As[kk][mm] = v;
        }
        #pragma unroll
        for (int i=0;i<8;i++){
            int idx = tid + i*256;
            int kk = idx & 31, nn = idx >> 5;
            Bs[kk][nn] = (k0+kk < K1) ? W1[(size_t)(bn+nn)*K1 + k0+kk] : 0.f;
        }
        __syncthreads();
        #pragma unroll
        for (int kk=0;kk<32;kk++){
            float4 a = *(const float4*)&As[kk][ty*4];
            ulonglong2 b = *(const ulonglong2*)&Bs[kk][tx*4];
            u64t pa0 = pk2(a.x,a.x), pa1 = pk2(a.y,a.y);
            u64t pa2 = pk2(a.z,a.z), pa3 = pk2(a.w,a.w);
            ffma2(acc[0][0], pa0, b.x); ffma2(acc[0][1], pa0, b.y);
            ffma2(acc[1][0], pa1, b.x); ffma2(acc[1][1], pa1, b.y);
            ffma2(acc[2][0], pa2, b.x); ffma2(acc[2][1], pa2, b.y);
            ffma2(acc[3][0], pa3, b.x); ffma2(acc[3][1], pa3, b.y);
        }
        __syncthreads();
    }
    #pragma unroll
    for (int i=0;i<4;i++){
        int row = bm + ty*4 + i;
        #pragma unroll
        for (int p=0;p<2;p++){
            float2 v = upk2(acc[i][p]);
            int n = bn + tx*4 + 2*p;
            pre[(size_t)row*N1 + n]     = sigmoidf_(v.x + b1[n]);
            pre[(size_t)row*N1 + n + 1] = sigmoidf_(v.y + b1[n+1]);
        }
    }
}

// ---------------------------------------------------------------------------
// Kernel 4: preds[row,d] = mask ? pre[row,:] . w2[d,:] + b2[d] : 0
// M=65280, N=128, K=1280.  f32x2 micro.  Writes directly into d_out.
// ---------------------------------------------------------------------------
__global__ __launch_bounds__(256) void gemm_preds(
    const float* __restrict__ pre, const float* __restrict__ W2,
    const float* __restrict__ b2, const int* __restrict__ lengths,
    float* __restrict__ out)
{
    __shared__ float As[32][68];
    __shared__ float Bs[32][68];
    const int bm = blockIdx.y*64;
    const int bn = blockIdx.x*64;
    const int tid = threadIdx.x;
    const int tx = tid & 15, ty = tid >> 4;
    u64t acc[4][2] = {};
    for (int k0 = 0; k0 < N1; k0 += 32){
        #pragma unroll
        for (int i=0;i<8;i++){
            int idx = tid + i*256;
            int kk = idx & 31, mm = idx >> 5;
            As[kk][mm] = pre[(size_t)(bm+mm)*N1 + k0+kk];
        }
        #pragma unroll
        for (int i=0;i<8;i++){
            int idx = tid + i*256;
            int kk = idx & 31, nn = idx >> 5;
            Bs[kk][nn] = W2[(size_t)(bn+nn)*N1 + k0+kk];
        }
        __syncthreads();
        #pragma unroll
        for (int kk=0;kk<32;kk++){
            float4 a = *(const float4*)&As[kk][ty*4];
            ulonglong2 b = *(const ulonglong2*)&Bs[kk][tx*4];
            u64t pa0 = pk2(a.x,a.x), pa1 = pk2(a.y,a.y);
            u64t pa2 = pk2(a.z,a.z), pa3 = pk2(a.w,a.w);
            ffma2(acc[0][0], pa0, b.x); ffma2(acc[0][1], pa0, b.y);
            ffma2(acc[1][0], pa1, b.x); ffma2(acc[1][1], pa1, b.y);
            ffma2(acc[2][0], pa2, b.x); ffma2(acc[2][1], pa2, b.y);
            ffma2(acc[3][0], pa3, b.x); ffma2(acc[3][1], pa3, b.y);
        }
        __syncthreads();
    }
    #pragma unroll
    for (int i=0;i<4;i++){
        int row = bm + ty*4 + i;
        int b = row / TM1;
        int tt = row - b*TM1;
        bool m = tt < (lengths[b] - 1);
        #pragma unroll
        for (int p=0;p<2;p++){
            float2 v = upk2(acc[i][p]);
            int n = bn + tx*4 + 2*p;
            out[(size_t)row*DOUT + n]     = m ? (v.x + b2[n])   : 0.f;
            out[(size_t)row*DOUT + n + 1] = m ? (v.y + b2[n+1]) : 0.f;
        }
    }
}

// ---------------------------------------------------------------------------
// Kernel 5: dist_params[b,p] = exp(-(h_last[b,:].wp[p,:] + bp[p]));
//           out lengths as float.
// ---------------------------------------------------------------------------
__global__ __launch_bounds__(256) void finalize_k(
    const float* __restrict__ h_last, const float* __restrict__ wp,
    const float* __restrict__ bp, const int* __restrict__ lengths,
    float* __restrict__ out)
{
    int b = threadIdx.x;
    if (b < BB){
        #pragma unroll
        for (int p=0;p<3;p++){
            float dot = 0.f;
            for (int h=0;h<HH;h++) dot += h_last[b*HH + h]*wp[p*HH + h];
            out[OFF_DIST + (size_t)b*3 + p] = expf(-(dot + bp[p]));
        }
        out[OFF_LEN + b] = (float)lengths[b];
    }
}

// ---------------------------------------------------------------------------
extern "C" void kernel_launch(void* const* d_in, const int* in_sizes, int n_in,
                              void* d_out, int out_size)
{
    const float* x    = (const float*)d_in[0];
    const float* h0   = (const float*)d_in[1];
    const int*   len  = (const int*)d_in[2];
    const float* w_ih = (const float*)d_in[3];
    const float* w_hh = (const float*)d_in[4];
    const float* b_ih = (const float*)d_in[5];
    const float* b_hh = (const float*)d_in[6];
    const float* w1   = (const float*)d_in[7];
    const float* b1   = (const float*)d_in[8];
    const float* w2   = (const float*)d_in[9];
    const float* b2   = (const float*)d_in[10];
    const float* wp   = (const float*)d_in[11];
    const float* bp   = (const float*)d_in[12];
    float* out = (float*)d_out;

    float *xw, *hidden, *hA, *hB, *pre;
    cudaGetSymbolAddress((void**)&xw,     g_xw);
    cudaGetSymbolAddress((void**)&hidden, g_hidden);
    cudaGetSymbolAddress((void**)&hA,     g_hA);
    cudaGetSymbolAddress((void**)&hB,     g_hB);
    cudaGetSymbolAddress((void**)&pre,    g_pre);

    // 1) input projection for all timesteps
    gemm_xw<<<dim3(GG/64, (TT*BB)/64), 256>>>(x, w_ih, b_ih, xw);

    // 2) sequential GRU with ping-pong h buffers
    const float* cur = h0;
    for (int t = 0; t < TT; t++){
        float* nxt = (t & 1) ? hB : hA;
        gru_step<<<dim3(16, 8), 256>>>(
            xw + (size_t)t*BB*GG, cur, nxt, hidden, w_hh, b_hh, len, t);
        cur = nxt;
    }

    // 3) MLP head
    gemm_pre<<<dim3(N1/64, M_PRE/64), 256>>>(hidden, x, w1, b1, pre);
    gemm_preds<<<dim3(DOUT/64, M_PRE/64), 256>>>(pre, w2, b2, len, out);

    // 4) distribution head + lengths passthrough
    finalize_k<<<1, 256>>>(cur, wp, bp, len, out);
}